// round 16
// baseline (speedup 1.0000x reference)
#include <cuda_runtime.h>
#include <math.h>

#define NNODE 20
#define NEDGE 380
#define HID   64
#define NL    3
#define ETILE 64
#define NTILE 6      // ceil(380/64)
#define SH    68     // stride for h-like [20][*] arrays (float4-aligned)
#define SMM   68     // buf edge-major stride (float4 aligned)
#define BLK   256
#define NB    1024

__device__ __forceinline__ float tanh_a(float v){
    float r; asm("tanh.approx.f32 %0, %1;" : "=f"(r) : "f"(v)); return r;
}
__device__ __forceinline__ float silu_f(float v){
    return __fdividef(v, 1.f + __expf(-v));
}
__device__ __forceinline__ float sigm_f(float v){
    return __fdividef(1.f, 1.f + __expf(-v));
}
__device__ __forceinline__ float tf32r(float v){
    unsigned int u; asm("cvt.rna.tf32.f32 %0, %1;" : "=r"(u) : "f"(v));
    return __uint_as_float(u);
}
__device__ __forceinline__ void mma_tf32(float d[4],
                                         unsigned int a0, unsigned int a1,
                                         unsigned int a2, unsigned int a3,
                                         unsigned int b0, unsigned int b1){
    asm volatile(
        "mma.sync.aligned.m16n8k8.row.col.f32.tf32.tf32.f32 "
        "{%0,%1,%2,%3}, {%4,%5,%6,%7}, {%8,%9}, {%0,%1,%2,%3};"
        : "+f"(d[0]), "+f"(d[1]), "+f"(d[2]), "+f"(d[3])
        : "r"(a0), "r"(a1), "r"(a2), "r"(a3), "r"(b0), "r"(b1));
}

// ---- fragment-packed tf32 weight scratch -------------------------------
// edge layout: index = ((((l*2 + nh)*8 + kt)*4 + nt)*32 + lane)*2 + j
__device__ float W2pk_g[12288];
__device__ float C1pk_g[12288];
// node layout (generic): idx = ((kt*(N/8) + nt)*32 + lane)*2 + j
__device__ float EW1pk_g[24576];   // per l: K=64, N=128 ([hA|hB] fused), 8192
__device__ float NW1pk_g[24576];   // per l: K=128, N=64, 8192
__device__ float NW2pk_g[12288];   // per l: K=64, N=64, 4096
__device__ float FC1pk_g[4096];    // K=64, N=64 (fc1w rows 1..64)

__global__ void pack_mma_kernel(const float* __restrict__ ew2,
                                const float* __restrict__ cw1){
    int i = blockIdx.x*blockDim.x + threadIdx.x;
    if (i < 12288){
        int j    = i & 1;
        int lane = (i >> 1) & 31;
        int nt   = (i >> 6) & 3;
        int kt   = (i >> 8) & 7;
        int nh   = (i >> 11) & 1;
        int l    = i >> 12;
        int k = kt*8 + (lane & 3) + j*4;
        int n = nh*32 + nt*8 + (lane >> 2);
        W2pk_g[i] = tf32r(ew2[l*4096 + k*64 + n]);
        C1pk_g[i] = tf32r(cw1[l*4096 + k*64 + n]);
    }
}

__global__ void pack_node_kernel(const float* __restrict__ ew1,
                                 const float* __restrict__ nw1,
                                 const float* __restrict__ nw2,
                                 const float* __restrict__ fc1w){
    int i = blockIdx.x*blockDim.x + threadIdx.x;
    if (i < 24576){
        int l = i / 8192, r = i % 8192;
        int j = r & 1, lane = (r >> 1) & 31, nt = (r >> 6) & 15, kt = r >> 10;
        int k = kt*8 + (lane & 3) + j*4;
        int n = nt*8 + (lane >> 2);
        const float* src = ew1 + l*8256;   // 129*64
        float v = (n < 64) ? src[k*64 + n] : src[(64 + k)*64 + (n - 64)];
        EW1pk_g[i] = tf32r(v);
    } else if (i < 49152){
        int r0 = i - 24576;
        int l = r0 / 8192, r = r0 % 8192;
        int j = r & 1, lane = (r >> 1) & 31, nt = (r >> 6) & 7, kt = r >> 9;
        int k = kt*8 + (lane & 3) + j*4;
        int n = nt*8 + (lane >> 2);
        NW1pk_g[r0] = tf32r(nw1[l*8192 + k*64 + n]);
    } else if (i < 61440){
        int r0 = i - 49152;
        int l = r0 / 4096, r = r0 % 4096;
        int j = r & 1, lane = (r >> 1) & 31, nt = (r >> 6) & 7, kt = r >> 9;
        int k = kt*8 + (lane & 3) + j*4;
        int n = nt*8 + (lane >> 2);
        NW2pk_g[r0] = tf32r(nw2[l*4096 + k*64 + n]);
    } else if (i < 65536){
        int r = i - 61440;
        int j = r & 1, lane = (r >> 1) & 31, nt = (r >> 6) & 7, kt = r >> 9;
        int k = kt*8 + (lane & 3) + j*4;
        int n = nt*8 + (lane >> 2);
        FC1pk_g[r] = tf32r(fc1w[(1 + k)*64 + n]);
    }
}

// smem: +attS[64] +wpS[64]
#define SMEM_FLOATS (80 + 4*NNODE*SH + ETILE*SMM + 6*64 + 2*ETILE + 384 + 128)

__global__ void __launch_bounds__(BLK, 4)
egnn_critic_kernel(
    const float* __restrict__ obs,   const float* __restrict__ rnn,
    const float* __restrict__ emb_w, const float* __restrict__ emb_b,
    const float* __restrict__ ew1,   const float* __restrict__ eb1,
    const float* __restrict__ ew2,   const float* __restrict__ eb2,
    const float* __restrict__ attw,  const float* __restrict__ attb,
    const float* __restrict__ nw1,   const float* __restrict__ nb1,
    const float* __restrict__ nw2,   const float* __restrict__ nb2,
    const float* __restrict__ cw1,   const float* __restrict__ cb1,
    const float* __restrict__ cw2,
    const float* __restrict__ fc1w,  const float* __restrict__ fc1b,
    const float* __restrict__ fc2w,  const float* __restrict__ fc2b,
    float* __restrict__ out, int copy_rnn)
{
    extern __shared__ float sm[];
    float* x0   = sm;
    float* x1   = x0 + NNODE;
    float* aggx = x1 + NNODE;
    float* aggy = aggx + NNODE;
    float* hS   = aggy + NNODE;          // [20][SH]
    float* hA   = hS + NNODE*SH;
    float* hB   = hA + NNODE*SH;
    float* mag  = hB + NNODE*SH;
    float* buf  = mag + NNODE*SH;        // A1 / Mm edge-major [64][SMM]
    float* w1c  = buf + ETILE*SMM;
    float* b1v  = w1c + 64;
    float* b2v  = b1v + 64;
    float* avv  = b2v + 64;
    float* cb1v = avv + 64;
    float* c2v  = cb1v + 64;
    float* cdx  = c2v + 64;
    float* cdy  = cdx + ETILE;
    short* rS   = (short*)(cdy + ETILE);      // [380]
    short* cS   = rS + 384;                   // [380]
    float* attS = (float*)(cS + 384);         // [64]
    float* wpS  = attS + 64;                  // [64]

    const int g = blockIdx.x;
    const int t = threadIdx.x;
    const int w = t >> 5, lane = t & 31;
    const int mt = w & 1, nc = w >> 1;        // node-GEMM warp mapping
    const int grp = lane >> 2, tig = lane & 3;
    const int r0 = 16*mt + grp;               // node rows r0, r0+8
    const int eb = (w & 3) << 4;              // edge-GEMM: edge block base
    const int nh = (w >> 2) << 5;             // edge-GEMM: n-half base
    const float* ob = obs + g * NNODE * 10;

    // ---- edge index tables (per block, once) ----
    for (int e = t; e < NEDGE; e += BLK){
        int r = e / 19, jj = e - 19*r;
        rS[e] = (short)r;
        cS[e] = (short)(jj + (jj >= r));
    }
    // ---- init x, h ----
    if (t < NNODE){ x0[t] = ob[t*10 + 0]; x1[t] = ob[t*10 + 1]; }
    {
        int d = t & 63, ng = t >> 6;
        #pragma unroll
        for (int q = 0; q < 5; ++q){
            int n = ng + 4*q;
            float acc = emb_b[d];
            #pragma unroll
            for (int k = 0; k < 8; ++k) acc += ob[n*10 + 2 + k] * __ldg(emb_w + k*64 + d);
            hS[n*SH + d] = acc;
        }
    }
    __syncthreads();

    for (int l = 0; l < NL; ++l){
        // ---- stage per-layer vectors, zero accumulators ----
        if (t < 64){
            w1c[t]  = ew1[l*129*64 + 128*64 + t];
            b1v[t]  = eb1[l*64 + t];
            b2v[t]  = eb2[l*64 + t];
            avv[t]  = attw[l*64 + t];
            cb1v[t] = cb1[l*64 + t];
            c2v[t]  = cw2[l*64 + t];
        }
        if (t < NNODE){ aggx[t] = 0.f; aggy[t] = 0.f; }
        for (int i = t; i < NNODE*SH; i += BLK) mag[i] = 0.f;
        __syncthreads();

        const float ab = __ldg(attb + l);

        // ---- hA|hB = h @ [W1a|W1b] via MMA (N=128; b1 folded into hA) ----
        {
            float d[4][4];
            #pragma unroll
            for (int q = 0; q < 4; ++q){ d[q][0]=0.f; d[q][1]=0.f; d[q][2]=0.f; d[q][3]=0.f; }
            const float* Ab = hS + r0*SH + tig;
            const float* Bpk = EW1pk_g + l*8192;
            #pragma unroll
            for (int kt = 0; kt < 8; ++kt){
                unsigned int a0 = __float_as_uint(Ab[kt*8]);
                unsigned int a1 = __float_as_uint(Ab[8*SH + kt*8]);
                unsigned int a2 = __float_as_uint(Ab[kt*8 + 4]);
                unsigned int a3 = __float_as_uint(Ab[8*SH + kt*8 + 4]);
                #pragma unroll
                for (int q = 0; q < 4; ++q){
                    int nt = nc*4 + q;
                    float2 bv = __ldg(reinterpret_cast<const float2*>(Bpk) + (kt*16 + nt)*32 + lane);
                    mma_tf32(d[q], a0, a1, a2, a3,
                             __float_as_uint(bv.x), __float_as_uint(bv.y));
                }
            }
            __syncthreads();
            #pragma unroll
            for (int q = 0; q < 4; ++q){
                int n = nc*32 + q*8 + 2*tig;
                bool isA = (n < 64);
                float* dst = isA ? hA : hB;
                int col = isA ? n : n - 64;
                float bb0 = isA ? b1v[col]     : 0.f;
                float bb1 = isA ? b1v[col + 1] : 0.f;
                if (r0 < NNODE){
                    dst[r0*SH + col]     = d[q][0] + bb0;
                    dst[r0*SH + col + 1] = d[q][1] + bb1;
                }
                if (r0 + 8 < NNODE){
                    dst[(r0+8)*SH + col]     = d[q][2] + bb0;
                    dst[(r0+8)*SH + col + 1] = d[q][3] + bb1;
                }
            }
        }
        __syncthreads();

        const float* W2pk = W2pk_g + (l*2 + (w >> 2))*2048;
        const float* C1pk = C1pk_g + (l*2 + (w >> 2))*2048;

        // ---- edge tiles (64 edges) ----
        for (int tile = 0; tile < NTILE; ++tile){
            const int e0 = tile * ETILE;

            // S0: build A1 = tf32(silu(hA[r] + hB[c] + radial*w1c)); zero attS
            {
                int le = t & 63, kg = t >> 6;
                int e = e0 + le;
                bool v = (e < NEDGE);
                int r = 0, c = 0; float radial = 0.f;
                if (v){
                    r = rS[e]; c = cS[e];
                    float dx = x0[r] - x0[c], dy = x1[r] - x1[c];
                    radial = dx*dx + dy*dy;
                    if (kg == 0){
                        float inv = 1.f / (sqrtf(radial) + 1e-8f);
                        cdx[le] = dx * inv; cdy[le] = dy * inv;
                    }
                }
                if (t < 64) attS[t] = 0.f;
                int kbeg = kg * 16;
                #pragma unroll 4
                for (int k4 = kbeg; k4 < kbeg + 16; k4 += 4){
                    float4 o4 = make_float4(0.f, 0.f, 0.f, 0.f);
                    if (v){
                        float4 ha = *(const float4*)(hA + r*SH + k4);
                        float4 hb = *(const float4*)(hB + c*SH + k4);
                        float4 wc = *(const float4*)(w1c + k4);
                        o4.x = tf32r(silu_f(fmaf(radial, wc.x, ha.x + hb.x)));
                        o4.y = tf32r(silu_f(fmaf(radial, wc.y, ha.y + hb.y)));
                        o4.z = tf32r(silu_f(fmaf(radial, wc.z, ha.z + hb.z)));
                        o4.w = tf32r(silu_f(fmaf(radial, wc.w, ha.w + hb.w)));
                    }
                    *(float4*)(buf + le*SMM + k4) = o4;
                }
            }
            __syncthreads();   // S1

            // GEMM1 fused: D = A1@W2 in regs; silu; att partials -> attS
            float d1[4][4];
            {
                #pragma unroll
                for (int nt = 0; nt < 4; ++nt){
                    d1[nt][0]=0.f; d1[nt][1]=0.f; d1[nt][2]=0.f; d1[nt][3]=0.f;
                }
                const float* Ab = buf + (eb + grp)*SMM + tig;
                #pragma unroll
                for (int kt = 0; kt < 8; ++kt){
                    unsigned int a0 = __float_as_uint(Ab[kt*8]);
                    unsigned int a1 = __float_as_uint(Ab[8*SMM + kt*8]);
                    unsigned int a2 = __float_as_uint(Ab[kt*8 + 4]);
                    unsigned int a3 = __float_as_uint(Ab[8*SMM + kt*8 + 4]);
                    const float2* Bk = reinterpret_cast<const float2*>(W2pk + kt*256) + lane;
                    #pragma unroll
                    for (int nt = 0; nt < 4; ++nt){
                        float2 bv = __ldg(Bk + nt*32);
                        mma_tf32(d1[nt], a0, a1, a2, a3,
                                 __float_as_uint(bv.x), __float_as_uint(bv.y));
                    }
                }
                float ap0 = 0.f, ap1 = 0.f;
                #pragma unroll
                for (int nt = 0; nt < 4; ++nt){
                    int col = nh + nt*8 + 2*tig;
                    float z0 = silu_f(d1[nt][0] + b2v[col]);
                    float z1 = silu_f(d1[nt][1] + b2v[col+1]);
                    float z2 = silu_f(d1[nt][2] + b2v[col]);
                    float z3 = silu_f(d1[nt][3] + b2v[col+1]);
                    d1[nt][0] = z0; d1[nt][1] = z1; d1[nt][2] = z2; d1[nt][3] = z3;
                    ap0 = fmaf(z0, avv[col], fmaf(z1, avv[col+1], ap0));
                    ap1 = fmaf(z2, avv[col], fmaf(z3, avv[col+1], ap1));
                }
                ap0 += __shfl_xor_sync(0xffffffffu, ap0, 1, 4);
                ap0 += __shfl_xor_sync(0xffffffffu, ap0, 2, 4);
                ap1 += __shfl_xor_sync(0xffffffffu, ap1, 1, 4);
                ap1 += __shfl_xor_sync(0xffffffffu, ap1, 2, 4);
                if (tig == 0){
                    atomicAdd(attS + eb + grp, ap0);
                    atomicAdd(attS + eb + grp + 8, ap1);
                }
            }
            __syncthreads();   // S2 (also: all A1 reads complete)

            // gate + store Mm (tf32) + m_agg atomics; zero wpS
            {
                float sg0 = sigm_f(attS[eb + grp] + ab);
                float sg1 = sigm_f(attS[eb + grp + 8] + ab);
                int ea = e0 + eb + grp, ebg = ea + 8;
                bool va = (ea < NEDGE), vb = (ebg < NEDGE);
                int ra = va ? rS[ea] : 0, rb = vb ? rS[ebg] : 0;
                if (t < 64) wpS[t] = 0.f;
                #pragma unroll
                for (int nt = 0; nt < 4; ++nt){
                    int col = nh + nt*8 + 2*tig;
                    float m0 = d1[nt][0]*sg0, m1 = d1[nt][1]*sg0;
                    float m2 = d1[nt][2]*sg1, m3 = d1[nt][3]*sg1;
                    *(float2*)(buf + (eb+grp)*SMM + col)   = make_float2(tf32r(m0), tf32r(m1));
                    *(float2*)(buf + (eb+grp+8)*SMM + col) = make_float2(tf32r(m2), tf32r(m3));
                    if (va){
                        atomicAdd(mag + ra*SH + col,     m0);
                        atomicAdd(mag + ra*SH + col + 1, m1);
                    }
                    if (vb){
                        atomicAdd(mag + rb*SH + col,     m2);
                        atomicAdd(mag + rb*SH + col + 1, m3);
                    }
                }
            }
            __syncthreads();   // S3

            // GEMM2 fused: D = Mm@C1 in regs; wp partials -> wpS
            {
                float d2[4][4];
                #pragma unroll
                for (int nt = 0; nt < 4; ++nt){
                    d2[nt][0]=0.f; d2[nt][1]=0.f; d2[nt][2]=0.f; d2[nt][3]=0.f;
                }
                const float* Ab = buf + (eb + grp)*SMM + tig;
                #pragma unroll
                for (int kt = 0; kt < 8; ++kt){
                    unsigned int a0 = __float_as_uint(Ab[kt*8]);
                    unsigned int a1 = __float_as_uint(Ab[8*SMM + kt*8]);
                    unsigned int a2 = __float_as_uint(Ab[kt*8 + 4]);
                    unsigned int a3 = __float_as_uint(Ab[8*SMM + kt*8 + 4]);
                    const float2* Bk = reinterpret_cast<const float2*>(C1pk + kt*256) + lane;
                    #pragma unroll
                    for (int nt = 0; nt < 4; ++nt){
                        float2 bv = __ldg(Bk + nt*32);
                        mma_tf32(d2[nt], a0, a1, a2, a3,
                                 __float_as_uint(bv.x), __float_as_uint(bv.y));
                    }
                }
                float wp0 = 0.f, wp1 = 0.f;
                #pragma unroll
                for (int nt = 0; nt < 4; ++nt){
                    int col = nh + nt*8 + 2*tig;
                    float z0 = silu_f(d2[nt][0] + cb1v[col]);
                    float z1 = silu_f(d2[nt][1] + cb1v[col+1]);
                    float z2 = silu_f(d2[nt][2] + cb1v[col]);
                    float z3 = silu_f(d2[nt][3] + cb1v[col+1]);
                    wp0 = fmaf(z0, c2v[col], fmaf(z1, c2v[col+1], wp0));
                    wp1 = fmaf(z2, c2v[col], fmaf(z3, c2v[col+1], wp1));
                }
                wp0 += __shfl_xor_sync(0xffffffffu, wp0, 1, 4);
                wp0 += __shfl_xor_sync(0xffffffffu, wp0, 2, 4);
                wp1 += __shfl_xor_sync(0xffffffffu, wp1, 1, 4);
                wp1 += __shfl_xor_sync(0xffffffffu, wp1, 2, 4);
                if (tig == 0){
                    atomicAdd(wpS + eb + grp, wp0);
                    atomicAdd(wpS + eb + grp + 8, wp1);
                }
            }
            __syncthreads();   // S4

            // scatter coords (t<64: one edge each)
            if (t < 64){
                int e = e0 + t;
                if (e < NEDGE){
                    float ww = tanh_a(wpS[t]);
                    int r = rS[e];
                    atomicAdd(aggx + r, cdx[t] * ww);
                    atomicAdd(aggy + r, cdy[t] * ww);
                }
            }
            __syncthreads();   // S5: protect buf/cdx/cdy/wpS before next tile
        } // tiles

        // ---- x update (cnt == 19 exactly) ----
        if (t < NNODE){
            x0[t] += aggx[t] * (1.f/19.f);
            x1[t] += aggy[t] * (1.f/19.f);
        }

        // ---- node MLP pass1 via MMA: z1 = silu([h,m_agg] @ nw1 + nb1)  (K=128)
        float* z1 = buf;
        {
            float d[2][4];
            d[0][0]=0.f; d[0][1]=0.f; d[0][2]=0.f; d[0][3]=0.f;
            d[1][0]=0.f; d[1][1]=0.f; d[1][2]=0.f; d[1][3]=0.f;
            const float* Bpk = NW1pk_g + l*8192;
            const float* Ab1 = hS  + r0*SH + tig;
            const float* Ab2 = mag + r0*SH + tig;
            #pragma unroll
            for (int kt = 0; kt < 16; ++kt){
                const float* Ab = (kt < 8) ? Ab1 : Ab2;
                int kk = (kt < 8) ? kt : kt - 8;
                unsigned int a0 = __float_as_uint(Ab[kk*8]);
                unsigned int a1 = __float_as_uint(Ab[8*SH + kk*8]);
                unsigned int a2 = __float_as_uint(Ab[kk*8 + 4]);
                unsigned int a3 = __float_as_uint(Ab[8*SH + kk*8 + 4]);
                #pragma unroll
                for (int q = 0; q < 2; ++q){
                    int nt = nc*2 + q;
                    float2 bv = __ldg(reinterpret_cast<const float2*>(Bpk) + (kt*8 + nt)*32 + lane);
                    mma_tf32(d[q], a0, a1, a2, a3,
                             __float_as_uint(bv.x), __float_as_uint(bv.y));
                }
            }
            __syncthreads();
            #pragma unroll
            for (int q = 0; q < 2; ++q){
                int c = nc*16 + q*8 + 2*tig;
                float bb0 = __ldg(nb1 + l*64 + c);
                float bb1 = __ldg(nb1 + l*64 + c + 1);
                if (r0 < NNODE){
                    z1[r0*SH + c]     = silu_f(d[q][0] + bb0);
                    z1[r0*SH + c + 1] = silu_f(d[q][1] + bb1);
                }
                if (r0 + 8 < NNODE){
                    z1[(r0+8)*SH + c]     = silu_f(d[q][2] + bb0);
                    z1[(r0+8)*SH + c + 1] = silu_f(d[q][3] + bb1);
                }
            }
        }
        __syncthreads();

        // ---- node MLP pass2 via MMA: h += z1 @ nw2 + nb2  (K=64) ----
        {
            float d[2][4];
            d[0][0]=0.f; d[0][1]=0.f; d[0][2]=0.f; d[0][3]=0.f;
            d[1][0]=0.f; d[1][1]=0.f; d[1][2]=0.f; d[1][3]=0.f;
            const float* Bpk = NW2pk_g + l*4096;
            const float* Ab = z1 + r0*SH + tig;
            #pragma unroll
            for (int kt = 0; kt < 8; ++kt){
                unsigned int a0 = __float_as_uint(Ab[kt*8]);
                unsigned int a1 = __float_as_uint(Ab[8*SH + kt*8]);
                unsigned int a2 = __float_as_uint(Ab[kt*8 + 4]);
                unsigned int a3 = __float_as_uint(Ab[8*SH + kt*8 + 4]);
                #pragma unroll
                for (int q = 0; q < 2; ++q){
                    int nt = nc*2 + q;
                    float2 bv = __ldg(reinterpret_cast<const float2*>(Bpk) + (kt*8 + nt)*32 + lane);
                    mma_tf32(d[q], a0, a1, a2, a3,
                             __float_as_uint(bv.x), __float_as_uint(bv.y));
                }
            }
            __syncthreads();
            #pragma unroll
            for (int q = 0; q < 2; ++q){
                int c = nc*16 + q*8 + 2*tig;
                float bb0 = __ldg(nb2 + l*64 + c);
                float bb1 = __ldg(nb2 + l*64 + c + 1);
                if (r0 < NNODE){
                    hS[r0*SH + c]     += d[q][0] + bb0;
                    hS[r0*SH + c + 1] += d[q][1] + bb1;
                }
                if (r0 + 8 < NNODE){
                    hS[(r0+8)*SH + c]     += d[q][2] + bb0;
                    hS[(r0+8)*SH + c + 1] += d[q][3] + bb1;
                }
            }
        }
        __syncthreads();
    } // layers

    // ---- value head via MMA: z1 = tanh([xsq,h] @ fc1w + fc1b) ----
    float* z1 = buf;
    {
        float d[2][4];
        d[0][0]=0.f; d[0][1]=0.f; d[0][2]=0.f; d[0][3]=0.f;
        d[1][0]=0.f; d[1][1]=0.f; d[1][2]=0.f; d[1][3]=0.f;
        const float* Ab = hS + r0*SH + tig;
        #pragma unroll
        for (int kt = 0; kt < 8; ++kt){
            unsigned int a0 = __float_as_uint(Ab[kt*8]);
            unsigned int a1 = __float_as_uint(Ab[8*SH + kt*8]);
            unsigned int a2 = __float_as_uint(Ab[kt*8 + 4]);
            unsigned int a3 = __float_as_uint(Ab[8*SH + kt*8 + 4]);
            #pragma unroll
            for (int q = 0; q < 2; ++q){
                int nt = nc*2 + q;
                float2 bv = __ldg(reinterpret_cast<const float2*>(FC1pk_g) + (kt*8 + nt)*32 + lane);
                mma_tf32(d[q], a0, a1, a2, a3,
                         __float_as_uint(bv.x), __float_as_uint(bv.y));
            }
        }
        __syncthreads();
        float xsq0 = 0.f, xsq1 = 0.f;
        if (r0 < NNODE)     xsq0 = x0[r0]*x0[r0] + x1[r0]*x1[r0];
        if (r0 + 8 < NNODE) xsq1 = x0[r0+8]*x0[r0+8] + x1[r0+8]*x1[r0+8];
        #pragma unroll
        for (int q = 0; q < 2; ++q){
            int c = nc*16 + q*8 + 2*tig;
            float w00 = __ldg(fc1w + c), w01 = __ldg(fc1w + c + 1);
            float bb0 = __ldg(fc1b + c), bb1 = __ldg(fc1b + c + 1);
            if (r0 < NNODE){
                z1[r0*SH + c]     = tanh_a(fmaf(xsq0, w00, d[q][0] + bb0));
                z1[r0*SH + c + 1] = tanh_a(fmaf(xsq0, w01, d[q][1] + bb1));
            }
            if (r0 + 8 < NNODE){
                z1[(r0+8)*SH + c]     = tanh_a(fmaf(xsq1, w00, d[q][2] + bb0));
                z1[(r0+8)*SH + c + 1] = tanh_a(fmaf(xsq1, w01, d[q][3] + bb1));
            }
        }
    }
    __syncthreads();
    if (t < 32){
        float v = 0.f;
        if (t < NNODE){
            v = __ldg(fc2b);
            #pragma unroll 4
            for (int k4 = 0; k4 < 64; k4 += 4){
                float4 z = *(const float4*)(z1 + t*SH + k4);
                float4 wv = *(const float4*)(fc2w + k4);
                v = fmaf(z.x, wv.x, v); v = fmaf(z.y, wv.y, v);
                v = fmaf(z.z, wv.z, v); v = fmaf(z.w, wv.w, v);
            }
        }
        #pragma unroll
        for (int m = 16; m >= 1; m >>= 1) v += __shfl_xor_sync(0xffffffffu, v, m);
        if (t == 0) out[g] = v * (1.f / NNODE);
    }
    // rnn_states passthrough
    if (copy_rnn && t < 64) out[NB + g*64 + t] = rnn[g*64 + t];
}

extern "C" void kernel_launch(void* const* d_in, const int* in_sizes, int n_in,
                              void* d_out, int out_size)
{
    const float* obs   = (const float*)d_in[0];
    const float* rnn   = (const float*)d_in[1];
    // d_in[2] = masks (unused)
    const float* emb_w = (const float*)d_in[3];
    const float* emb_b = (const float*)d_in[4];
    const float* ew1   = (const float*)d_in[5];
    const float* eb1   = (const float*)d_in[6];
    const float* ew2   = (const float*)d_in[7];
    const float* eb2   = (const float*)d_in[8];
    const float* attw  = (const float*)d_in[9];
    const float* attb  = (const float*)d_in[10];
    const float* nw1   = (const float*)d_in[11];
    const float* nb1   = (const float*)d_in[12];
    const float* nw2   = (const float*)d_in[13];
    const float* nb2   = (const float*)d_in[14];
    const float* cw1   = (const float*)d_in[15];
    const float* cb1   = (const float*)d_in[16];
    const float* cw2   = (const float*)d_in[17];
    const float* fc1w  = (const float*)d_in[18];
    const float* fc1b  = (const float*)d_in[19];
    const float* fc2w  = (const float*)d_in[20];
    const float* fc2b  = (const float*)d_in[21];
    // d_in[22], d_in[23] = edge_row/edge_col (recomputed analytically)

    pack_mma_kernel<<<48, 256>>>(ew2, cw1);
    pack_node_kernel<<<256, 256>>>(ew1, nw1, nw2, fc1w);

    const size_t smem_bytes = (size_t)SMEM_FLOATS * sizeof(float);
    cudaFuncSetAttribute(egnn_critic_kernel,
                         cudaFuncAttributeMaxDynamicSharedMemorySize,
                         (int)smem_bytes);

    int copy_rnn = (out_size >= NB + NB*HID) ? 1 : 0;

    egnn_critic_kernel<<<NB, BLK, smem_bytes>>>(
        obs, rnn, emb_w, emb_b, ew1, eb1, ew2, eb2, attw, attb,
        nw1, nb1, nw2, nb2, cw1, cb1, cw2, fc1w, fc1b, fc2w, fc2b,
        (float*)d_out, copy_rnn);
}

// round 17
// speedup vs baseline: 1.5359x; 1.5359x over previous
#include <cuda_runtime.h>
#include <math.h>

#define NNODE 20
#define NEDGE 380
#define HID   64
#define NL    3
#define ETILE 64
#define NTILE 6      // ceil(380/64)
#define SH    68     // stride for h-like [20][*] arrays (float4-aligned)
#define SMM   68     // buf edge-major stride (float4 aligned)
#define BLK   256
#define NB    1024

__device__ __forceinline__ float tanh_a(float v){
    float r; asm("tanh.approx.f32 %0, %1;" : "=f"(r) : "f"(v)); return r;
}
__device__ __forceinline__ float silu_f(float v){
    return __fdividef(v, 1.f + __expf(-v));
}
__device__ __forceinline__ float sigm_f(float v){
    return __fdividef(1.f, 1.f + __expf(-v));
}
__device__ __forceinline__ float tf32r(float v){
    unsigned int u; asm("cvt.rna.tf32.f32 %0, %1;" : "=r"(u) : "f"(v));
    return __uint_as_float(u);
}
__device__ __forceinline__ void mma_tf32(float d[4],
                                         unsigned int a0, unsigned int a1,
                                         unsigned int a2, unsigned int a3,
                                         unsigned int b0, unsigned int b1){
    asm volatile(
        "mma.sync.aligned.m16n8k8.row.col.f32.tf32.tf32.f32 "
        "{%0,%1,%2,%3}, {%4,%5,%6,%7}, {%8,%9}, {%0,%1,%2,%3};"
        : "+f"(d[0]), "+f"(d[1]), "+f"(d[2]), "+f"(d[3])
        : "r"(a0), "r"(a1), "r"(a2), "r"(a3), "r"(b0), "r"(b1));
}

// ---- fragment-packed tf32 weight scratch -------------------------------
// edge layout: index = ((((l*2 + nh)*8 + kt)*4 + nt)*32 + lane)*2 + j
__device__ float W2pk_g[12288];
__device__ float C1pk_g[12288];
// node layout (generic): idx = ((kt*(N/8) + nt)*32 + lane)*2 + j
__device__ float EW1pk_g[24576];   // per l: K=64, N=128 ([hA|hB] fused), 8192
__device__ float NW1pk_g[24576];   // per l: K=128, N=64, 8192
__device__ float NW2pk_g[12288];   // per l: K=64, N=64, 4096
__device__ float FC1pk_g[4096];    // K=64, N=64 (fc1w rows 1..64)

__global__ void pack_mma_kernel(const float* __restrict__ ew2,
                                const float* __restrict__ cw1){
    int i = blockIdx.x*blockDim.x + threadIdx.x;
    if (i < 12288){
        int j    = i & 1;
        int lane = (i >> 1) & 31;
        int nt   = (i >> 6) & 3;
        int kt   = (i >> 8) & 7;
        int nh   = (i >> 11) & 1;
        int l    = i >> 12;
        int k = kt*8 + (lane & 3) + j*4;
        int n = nh*32 + nt*8 + (lane >> 2);
        W2pk_g[i] = tf32r(ew2[l*4096 + k*64 + n]);
        C1pk_g[i] = tf32r(cw1[l*4096 + k*64 + n]);
    }
}

__global__ void pack_node_kernel(const float* __restrict__ ew1,
                                 const float* __restrict__ nw1,
                                 const float* __restrict__ nw2,
                                 const float* __restrict__ fc1w){
    int i = blockIdx.x*blockDim.x + threadIdx.x;
    if (i < 24576){
        int l = i / 8192, r = i % 8192;
        int j = r & 1, lane = (r >> 1) & 31, nt = (r >> 6) & 15, kt = r >> 10;
        int k = kt*8 + (lane & 3) + j*4;
        int n = nt*8 + (lane >> 2);
        const float* src = ew1 + l*8256;   // 129*64
        float v = (n < 64) ? src[k*64 + n] : src[(64 + k)*64 + (n - 64)];
        EW1pk_g[i] = tf32r(v);
    } else if (i < 49152){
        int r0 = i - 24576;
        int l = r0 / 8192, r = r0 % 8192;
        int j = r & 1, lane = (r >> 1) & 31, nt = (r >> 6) & 7, kt = r >> 9;
        int k = kt*8 + (lane & 3) + j*4;
        int n = nt*8 + (lane >> 2);
        NW1pk_g[r0] = tf32r(nw1[l*8192 + k*64 + n]);
    } else if (i < 61440){
        int r0 = i - 49152;
        int l = r0 / 4096, r = r0 % 4096;
        int j = r & 1, lane = (r >> 1) & 31, nt = (r >> 6) & 7, kt = r >> 9;
        int k = kt*8 + (lane & 3) + j*4;
        int n = nt*8 + (lane >> 2);
        NW2pk_g[r0] = tf32r(nw2[l*4096 + k*64 + n]);
    } else if (i < 65536){
        int r = i - 61440;
        int j = r & 1, lane = (r >> 1) & 31, nt = (r >> 6) & 7, kt = r >> 9;
        int k = kt*8 + (lane & 3) + j*4;
        int n = nt*8 + (lane >> 2);
        FC1pk_g[r] = tf32r(fc1w[(1 + k)*64 + n]);
    }
}

// smem: R15 layout + wpS[64]
#define SMEM_FLOATS (80 + 4*NNODE*SH + ETILE*SMM + 6*64 + 2*ETILE + 384 + 64)

// GEMM1 (unchanged from R15 champion): D = A1 @ Bpk -> buf
__device__ __forceinline__ void mma_gemm_64(float* buf, const float* Bpk,
                                            int t){
    int w = t >> 5, lane = t & 31;
    int eb = (w & 3) << 4;
    int nh = (w >> 2) << 5;
    int grp = lane >> 2, tig = lane & 3;
    float d[4][4];
    #pragma unroll
    for (int nt = 0; nt < 4; ++nt){
        d[nt][0] = 0.f; d[nt][1] = 0.f; d[nt][2] = 0.f; d[nt][3] = 0.f;
    }
    const float* Ab = buf + (eb + grp)*SMM + tig;
    #pragma unroll
    for (int kt = 0; kt < 8; ++kt){
        unsigned int a0 = __float_as_uint(Ab[kt*8]);
        unsigned int a1 = __float_as_uint(Ab[8*SMM + kt*8]);
        unsigned int a2 = __float_as_uint(Ab[kt*8 + 4]);
        unsigned int a3 = __float_as_uint(Ab[8*SMM + kt*8 + 4]);
        const float2* Bk = reinterpret_cast<const float2*>(Bpk + kt*256) + lane;
        #pragma unroll
        for (int nt = 0; nt < 4; ++nt){
            float2 bv = __ldg(Bk + nt*32);
            mma_tf32(d[nt], a0, a1, a2, a3,
                     __float_as_uint(bv.x), __float_as_uint(bv.y));
        }
    }
    __syncthreads();   // all A reads complete -> overwrite buf with D
    #pragma unroll
    for (int nt = 0; nt < 4; ++nt){
        int col = nh + nt*8 + 2*tig;
        float* p = buf + (eb + grp)*SMM + col;
        *(float2*)p            = make_float2(d[nt][0], d[nt][1]);
        *(float2*)(p + 8*SMM)  = make_float2(d[nt][2], d[nt][3]);
    }
}

__global__ void __launch_bounds__(BLK, 4)
egnn_critic_kernel(
    const float* __restrict__ obs,   const float* __restrict__ rnn,
    const float* __restrict__ emb_w, const float* __restrict__ emb_b,
    const float* __restrict__ ew1,   const float* __restrict__ eb1,
    const float* __restrict__ ew2,   const float* __restrict__ eb2,
    const float* __restrict__ attw,  const float* __restrict__ attb,
    const float* __restrict__ nw1,   const float* __restrict__ nb1,
    const float* __restrict__ nw2,   const float* __restrict__ nb2,
    const float* __restrict__ cw1,   const float* __restrict__ cb1,
    const float* __restrict__ cw2,
    const float* __restrict__ fc1w,  const float* __restrict__ fc1b,
    const float* __restrict__ fc2w,  const float* __restrict__ fc2b,
    float* __restrict__ out, int copy_rnn)
{
    extern __shared__ float sm[];
    float* x0   = sm;
    float* x1   = x0 + NNODE;
    float* aggx = x1 + NNODE;
    float* aggy = aggx + NNODE;
    float* hS   = aggy + NNODE;          // [20][SH]
    float* hA   = hS + NNODE*SH;
    float* hB   = hA + NNODE*SH;
    float* mag  = hB + NNODE*SH;
    float* buf  = mag + NNODE*SH;        // A1 / D / Mm edge-major [64][SMM]
    float* w1c  = buf + ETILE*SMM;
    float* b1v  = w1c + 64;
    float* b2v  = b1v + 64;
    float* avv  = b2v + 64;
    float* cb1v = avv + 64;
    float* c2v  = cb1v + 64;
    float* cdx  = c2v + 64;
    float* cdy  = cdx + ETILE;
    short* rS   = (short*)(cdy + ETILE);      // [380]
    short* cS   = rS + 384;                   // [380]
    float* wpS  = (float*)(cS + 384);         // [64]

    const int g = blockIdx.x;
    const int t = threadIdx.x;
    const int w = t >> 5, lane = t & 31;
    const int mt = w & 1, nc = w >> 1;        // node-GEMM warp mapping
    const int grp = lane >> 2, tig = lane & 3;
    const int r0 = 16*mt + grp;               // node rows r0, r0+8
    const int eb = (w & 3) << 4;              // edge-GEMM: edge block base
    const int nh = (w >> 2) << 5;             // edge-GEMM: n-half base
    const float* ob = obs + g * NNODE * 10;

    // ---- edge index tables (per block, once) ----
    for (int e = t; e < NEDGE; e += BLK){
        int r = e / 19, jj = e - 19*r;
        rS[e] = (short)r;
        cS[e] = (short)(jj + (jj >= r));
    }
    // ---- init x, h ----
    if (t < NNODE){ x0[t] = ob[t*10 + 0]; x1[t] = ob[t*10 + 1]; }
    {
        int d = t & 63, ng = t >> 6;
        #pragma unroll
        for (int q = 0; q < 5; ++q){
            int n = ng + 4*q;
            float acc = emb_b[d];
            #pragma unroll
            for (int k = 0; k < 8; ++k) acc += ob[n*10 + 2 + k] * __ldg(emb_w + k*64 + d);
            hS[n*SH + d] = acc;
        }
    }
    __syncthreads();

    for (int l = 0; l < NL; ++l){
        // ---- stage per-layer vectors, zero accumulators ----
        if (t < 64){
            w1c[t]  = ew1[l*129*64 + 128*64 + t];
            b1v[t]  = eb1[l*64 + t];
            b2v[t]  = eb2[l*64 + t];
            avv[t]  = attw[l*64 + t];
            cb1v[t] = cb1[l*64 + t];
            c2v[t]  = cw2[l*64 + t];
        }
        if (t < NNODE){ aggx[t] = 0.f; aggy[t] = 0.f; }
        for (int i = t; i < NNODE*SH; i += BLK) mag[i] = 0.f;
        __syncthreads();

        const float ab = __ldg(attb + l);

        // ---- hA|hB = h @ [W1a|W1b] via MMA (N=128; b1 folded into hA) ----
        {
            float d[4][4];
            #pragma unroll
            for (int q = 0; q < 4; ++q){ d[q][0]=0.f; d[q][1]=0.f; d[q][2]=0.f; d[q][3]=0.f; }
            const float* Ab = hS + r0*SH + tig;
            const float* Bpk = EW1pk_g + l*8192;
            #pragma unroll
            for (int kt = 0; kt < 8; ++kt){
                unsigned int a0 = __float_as_uint(Ab[kt*8]);
                unsigned int a1 = __float_as_uint(Ab[8*SH + kt*8]);
                unsigned int a2 = __float_as_uint(Ab[kt*8 + 4]);
                unsigned int a3 = __float_as_uint(Ab[8*SH + kt*8 + 4]);
                #pragma unroll
                for (int q = 0; q < 4; ++q){
                    int nt = nc*4 + q;
                    float2 bv = __ldg(reinterpret_cast<const float2*>(Bpk) + (kt*16 + nt)*32 + lane);
                    mma_tf32(d[q], a0, a1, a2, a3,
                             __float_as_uint(bv.x), __float_as_uint(bv.y));
                }
            }
            __syncthreads();
            #pragma unroll
            for (int q = 0; q < 4; ++q){
                int n = nc*32 + q*8 + 2*tig;
                bool isA = (n < 64);
                float* dst = isA ? hA : hB;
                int col = isA ? n : n - 64;
                float bb0 = isA ? b1v[col]     : 0.f;
                float bb1 = isA ? b1v[col + 1] : 0.f;
                if (r0 < NNODE){
                    dst[r0*SH + col]     = d[q][0] + bb0;
                    dst[r0*SH + col + 1] = d[q][1] + bb1;
                }
                if (r0 + 8 < NNODE){
                    dst[(r0+8)*SH + col]     = d[q][2] + bb0;
                    dst[(r0+8)*SH + col + 1] = d[q][3] + bb1;
                }
            }
        }
        __syncthreads();

        const float* W2pk = W2pk_g + (l*2)*2048;
        const float* C1pk = C1pk_g + (l*2 + (w >> 2))*2048;

        // ---- edge tiles (64 edges) ----
        for (int tile = 0; tile < NTILE; ++tile){
            const int e0 = tile * ETILE;

            // S0: build A1 = tf32(silu(hA[r] + hB[c] + radial*w1c))
            {
                int le = t & 63, kg = t >> 6;
                int e = e0 + le;
                bool v = (e < NEDGE);
                int r = 0, c = 0; float radial = 0.f;
                if (v){
                    r = rS[e]; c = cS[e];
                    float dx = x0[r] - x0[c], dy = x1[r] - x1[c];
                    radial = dx*dx + dy*dy;
                    if (kg == 0){
                        float inv = 1.f / (sqrtf(radial) + 1e-8f);
                        cdx[le] = dx * inv; cdy[le] = dy * inv;
                    }
                }
                int kbeg = kg * 16;
                #pragma unroll 4
                for (int k4 = kbeg; k4 < kbeg + 16; k4 += 4){
                    float4 o4 = make_float4(0.f, 0.f, 0.f, 0.f);
                    if (v){
                        float4 ha = *(const float4*)(hA + r*SH + k4);
                        float4 hb = *(const float4*)(hB + c*SH + k4);
                        float4 wc = *(const float4*)(w1c + k4);
                        o4.x = tf32r(silu_f(fmaf(radial, wc.x, ha.x + hb.x)));
                        o4.y = tf32r(silu_f(fmaf(radial, wc.y, ha.y + hb.y)));
                        o4.z = tf32r(silu_f(fmaf(radial, wc.z, ha.z + hb.z)));
                        o4.w = tf32r(silu_f(fmaf(radial, wc.w, ha.w + hb.w)));
                    }
                    *(float4*)(buf + le*SMM + k4) = o4;
                }
            }
            __syncthreads();

            // GEMM1 core (R15 proven): D = A1 @ W2 -> buf
            mma_gemm_64(buf, W2pk + ((w >> 2) ? 2048 : 0), t);
            __syncthreads();

            // epilogue 1 (R15 proven): m = silu(D + b2) * sigmoid(att);
            // Mm (tf32) in-place; fused m_agg segment sum; zero wpS
            {
                int tx = t & 15, ty = t >> 4;
                float mz[4][4];
                float attp[4];
                #pragma unroll
                for (int i = 0; i < 4; ++i){
                    float4 dv = *(const float4*)(buf + (4*ty+i)*SMM + 4*tx);
                    float z0 = silu_f(dv.x + b2v[4*tx + 0]);
                    float z1 = silu_f(dv.y + b2v[4*tx + 1]);
                    float z2 = silu_f(dv.z + b2v[4*tx + 2]);
                    float z3 = silu_f(dv.w + b2v[4*tx + 3]);
                    mz[i][0] = z0; mz[i][1] = z1; mz[i][2] = z2; mz[i][3] = z3;
                    attp[i] = z0*avv[4*tx+0] + z1*avv[4*tx+1]
                            + z2*avv[4*tx+2] + z3*avv[4*tx+3];
                }
                #pragma unroll
                for (int m = 8; m >= 1; m >>= 1){
                    #pragma unroll
                    for (int i = 0; i < 4; ++i)
                        attp[i] += __shfl_xor_sync(0xffffffffu, attp[i], m, 16);
                }
                float sg[4];
                #pragma unroll
                for (int i = 0; i < 4; ++i) sg[i] = sigm_f(attp[i] + ab);
                if (t < 64) wpS[t] = 0.f;

                float s0 = 0.f, s1 = 0.f, s2 = 0.f, s3 = 0.f;
                int curr = -1;
                #pragma unroll
                for (int i = 0; i < 4; ++i){
                    float m0 = mz[i][0]*sg[i], m1 = mz[i][1]*sg[i];
                    float m2 = mz[i][2]*sg[i], m3 = mz[i][3]*sg[i];
                    *(float4*)(buf + (4*ty + i)*SMM + 4*tx) =
                        make_float4(tf32r(m0), tf32r(m1), tf32r(m2), tf32r(m3));
                    int e = e0 + 4*ty + i;
                    if (e < NEDGE){
                        int r = rS[e];
                        if (r != curr){
                            if (curr >= 0){
                                atomicAdd(mag + curr*SH + 4*tx + 0, s0);
                                atomicAdd(mag + curr*SH + 4*tx + 1, s1);
                                atomicAdd(mag + curr*SH + 4*tx + 2, s2);
                                atomicAdd(mag + curr*SH + 4*tx + 3, s3);
                            }
                            curr = r; s0 = s1 = s2 = s3 = 0.f;
                        }
                        s0 += m0; s1 += m1; s2 += m2; s3 += m3;
                    }
                }
                if (curr >= 0){
                    atomicAdd(mag + curr*SH + 4*tx + 0, s0);
                    atomicAdd(mag + curr*SH + 4*tx + 1, s1);
                    atomicAdd(mag + curr*SH + 4*tx + 2, s2);
                    atomicAdd(mag + curr*SH + 4*tx + 3, s3);
                }
            }
            __syncthreads();

            // GEMM2 FUSED (R16 numerically proven): D2 in regs; wp -> wpS
            {
                float d2[4][4];
                #pragma unroll
                for (int nt = 0; nt < 4; ++nt){
                    d2[nt][0]=0.f; d2[nt][1]=0.f; d2[nt][2]=0.f; d2[nt][3]=0.f;
                }
                const float* Ab = buf + (eb + grp)*SMM + tig;
                #pragma unroll
                for (int kt = 0; kt < 8; ++kt){
                    unsigned int a0 = __float_as_uint(Ab[kt*8]);
                    unsigned int a1 = __float_as_uint(Ab[8*SMM + kt*8]);
                    unsigned int a2 = __float_as_uint(Ab[kt*8 + 4]);
                    unsigned int a3 = __float_as_uint(Ab[8*SMM + kt*8 + 4]);
                    const float2* Bk = reinterpret_cast<const float2*>(C1pk + kt*256) + lane;
                    #pragma unroll
                    for (int nt = 0; nt < 4; ++nt){
                        float2 bv = __ldg(Bk + nt*32);
                        mma_tf32(d2[nt], a0, a1, a2, a3,
                                 __float_as_uint(bv.x), __float_as_uint(bv.y));
                    }
                }
                float wp0 = 0.f, wp1 = 0.f;
                #pragma unroll
                for (int nt = 0; nt < 4; ++nt){
                    int col = nh + nt*8 + 2*tig;
                    float z0 = silu_f(d2[nt][0] + cb1v[col]);
                    float z1 = silu_f(d2[nt][1] + cb1v[col+1]);
                    float z2 = silu_f(d2[nt][2] + cb1v[col]);
                    float z3 = silu_f(d2[nt][3] + cb1v[col+1]);
                    wp0 = fmaf(z0, c2v[col], fmaf(z1, c2v[col+1], wp0));
                    wp1 = fmaf(z2, c2v[col], fmaf(z3, c2v[col+1], wp1));
                }
                wp0 += __shfl_xor_sync(0xffffffffu, wp0, 1, 4);
                wp0 += __shfl_xor_sync(0xffffffffu, wp0, 2, 4);
                wp1 += __shfl_xor_sync(0xffffffffu, wp1, 1, 4);
                wp1 += __shfl_xor_sync(0xffffffffu, wp1, 2, 4);
                if (tig == 0){
                    atomicAdd(wpS + eb + grp, wp0);
                    atomicAdd(wpS + eb + grp + 8, wp1);
                }
            }
            __syncthreads();

            // scatter coords (t<64: one edge each)
            if (t < 64){
                int e = e0 + t;
                if (e < NEDGE){
                    float ww = tanh_a(wpS[t]);
                    int r = rS[e];
                    atomicAdd(aggx + r, cdx[t] * ww);
                    atomicAdd(aggy + r, cdy[t] * ww);
                }
            }
            __syncthreads();   // protect buf/cdx/cdy/wpS before next tile
        } // tiles

        // ---- x update (cnt == 19 exactly) ----
        if (t < NNODE){
            x0[t] += aggx[t] * (1.f/19.f);
            x1[t] += aggy[t] * (1.f/19.f);
        }

        // ---- node MLP pass1 via MMA: z1 = silu([h,m_agg] @ nw1 + nb1)  (K=128)
        float* z1 = buf;
        {
            float d[2][4];
            d[0][0]=0.f; d[0][1]=0.f; d[0][2]=0.f; d[0][3]=0.f;
            d[1][0]=0.f; d[1][1]=0.f; d[1][2]=0.f; d[1][3]=0.f;
            const float* Bpk = NW1pk_g + l*8192;
            const float* Ab1 = hS  + r0*SH + tig;
            const float* Ab2 = mag + r0*SH + tig;
            #pragma unroll
            for (int kt = 0; kt < 16; ++kt){
                const float* Ab = (kt < 8) ? Ab1 : Ab2;
                int kk = (kt < 8) ? kt : kt - 8;
                unsigned int a0 = __float_as_uint(Ab[kk*8]);
                unsigned int a1 = __float_as_uint(Ab[8*SH + kk*8]);
                unsigned int a2 = __float_as_uint(Ab[kk*8 + 4]);
                unsigned int a3 = __float_as_uint(Ab[8*SH + kk*8 + 4]);
                #pragma unroll
                for (int q = 0; q < 2; ++q){
                    int nt = nc*2 + q;
                    float2 bv = __ldg(reinterpret_cast<const float2*>(Bpk) + (kt*8 + nt)*32 + lane);
                    mma_tf32(d[q], a0, a1, a2, a3,
                             __float_as_uint(bv.x), __float_as_uint(bv.y));
                }
            }
            __syncthreads();
            #pragma unroll
            for (int q = 0; q < 2; ++q){
                int c = nc*16 + q*8 + 2*tig;
                float bb0 = __ldg(nb1 + l*64 + c);
                float bb1 = __ldg(nb1 + l*64 + c + 1);
                if (r0 < NNODE){
                    z1[r0*SH + c]     = silu_f(d[q][0] + bb0);
                    z1[r0*SH + c + 1] = silu_f(d[q][1] + bb1);
                }
                if (r0 + 8 < NNODE){
                    z1[(r0+8)*SH + c]     = silu_f(d[q][2] + bb0);
                    z1[(r0+8)*SH + c + 1] = silu_f(d[q][3] + bb1);
                }
            }
        }
        __syncthreads();

        // ---- node MLP pass2 via MMA: h += z1 @ nw2 + nb2  (K=64) ----
        {
            float d[2][4];
            d[0][0]=0.f; d[0][1]=0.f; d[0][2]=0.f; d[0][3]=0.f;
            d[1][0]=0.f; d[1][1]=0.f; d[1][2]=0.f; d[1][3]=0.f;
            const float* Bpk = NW2pk_g + l*4096;
            const float* Ab = z1 + r0*SH + tig;
            #pragma unroll
            for (int kt = 0; kt < 8; ++kt){
                unsigned int a0 = __float_as_uint(Ab[kt*8]);
                unsigned int a1 = __float_as_uint(Ab[8*SH + kt*8]);
                unsigned int a2 = __float_as_uint(Ab[kt*8 + 4]);
                unsigned int a3 = __float_as_uint(Ab[8*SH + kt*8 + 4]);
                #pragma unroll
                for (int q = 0; q < 2; ++q){
                    int nt = nc*2 + q;
                    float2 bv = __ldg(reinterpret_cast<const float2*>(Bpk) + (kt*8 + nt)*32 + lane);
                    mma_tf32(d[q], a0, a1, a2, a3,
                             __float_as_uint(bv.x), __float_as_uint(bv.y));
                }
            }
            __syncthreads();
            #pragma unroll
            for (int q = 0; q < 2; ++q){
                int c = nc*16 + q*8 + 2*tig;
                float bb0 = __ldg(nb2 + l*64 + c);
                float bb1 = __ldg(nb2 + l*64 + c + 1);
                if (r0 < NNODE){
                    hS[r0*SH + c]     += d[q][0] + bb0;
                    hS[r0*SH + c + 1] += d[q][1] + bb1;
                }
                if (r0 + 8 < NNODE){
                    hS[(r0+8)*SH + c]     += d[q][2] + bb0;
                    hS[(r0+8)*SH + c + 1] += d[q][3] + bb1;
                }
            }
        }
        __syncthreads();
    } // layers

    // ---- value head via MMA: z1 = tanh([xsq,h] @ fc1w + fc1b) ----
    float* z1 = buf;
    {
        float d[2][4];
        d[0][0]=0.f; d[0][1]=0.f; d[0][2]=0.f; d[0][3]=0.f;
        d[1][0]=0.f; d[1][1]=0.f; d[1][2]=0.f; d[1][3]=0.f;
        const float* Ab = hS + r0*SH + tig;
        #pragma unroll
        for (int kt = 0; kt < 8; ++kt){
            unsigned int a0 = __float_as_uint(Ab[kt*8]);
            unsigned int a1 = __float_as_uint(Ab[8*SH + kt*8]);
            unsigned int a2 = __float_as_uint(Ab[kt*8 + 4]);
            unsigned int a3 = __float_as_uint(Ab[8*SH + kt*8 + 4]);
            #pragma unroll
            for (int q = 0; q < 2; ++q){
                int nt = nc*2 + q;
                float2 bv = __ldg(reinterpret_cast<const float2*>(FC1pk_g) + (kt*8 + nt)*32 + lane);
                mma_tf32(d[q], a0, a1, a2, a3,
                         __float_as_uint(bv.x), __float_as_uint(bv.y));
            }
        }
        __syncthreads();
        float xsq0 = 0.f, xsq1 = 0.f;
        if (r0 < NNODE)     xsq0 = x0[r0]*x0[r0] + x1[r0]*x1[r0];
        if (r0 + 8 < NNODE) xsq1 = x0[r0+8]*x0[r0+8] + x1[r0+8]*x1[r0+8];
        #pragma unroll
        for (int q = 0; q < 2; ++q){
            int c = nc*16 + q*8 + 2*tig;
            float w00 = __ldg(fc1w + c), w01 = __ldg(fc1w + c + 1);
            float bb0 = __ldg(fc1b + c), bb1 = __ldg(fc1b + c + 1);
            if (r0 < NNODE){
                z1[r0*SH + c]     = tanh_a(fmaf(xsq0, w00, d[q][0] + bb0));
                z1[r0*SH + c + 1] = tanh_a(fmaf(xsq0, w01, d[q][1] + bb1));
            }
            if (r0 + 8 < NNODE){
                z1[(r0+8)*SH + c]     = tanh_a(fmaf(xsq1, w00, d[q][2] + bb0));
                z1[(r0+8)*SH + c + 1] = tanh_a(fmaf(xsq1, w01, d[q][3] + bb1));
            }
        }
    }
    __syncthreads();
    if (t < 32){
        float v = 0.f;
        if (t < NNODE){
            v = __ldg(fc2b);
            #pragma unroll 4
            for (int k4 = 0; k4 < 64; k4 += 4){
                float4 z = *(const float4*)(z1 + t*SH + k4);
                float4 wv = *(const float4*)(fc2w + k4);
                v = fmaf(z.x, wv.x, v); v = fmaf(z.y, wv.y, v);
                v = fmaf(z.z, wv.z, v); v = fmaf(z.w, wv.w, v);
            }
        }
        #pragma unroll
        for (int m = 16; m >= 1; m >>= 1) v += __shfl_xor_sync(0xffffffffu, v, m);
        if (t == 0) out[g] = v * (1.f / NNODE);
    }
    // rnn_states passthrough
    if (copy_rnn && t < 64) out[NB + g*64 + t] = rnn[g*64 + t];
}

extern "C" void kernel_launch(void* const* d_in, const int* in_sizes, int n_in,
                              void* d_out, int out_size)
{
    const float* obs   = (const float*)d_in[0];
    const float* rnn   = (const float*)d_in[1];
    // d_in[2] = masks (unused)
    const float* emb_w = (const float*)d_in[3];
    const float* emb_b = (const float*)d_in[4];
    const float* ew1   = (const float*)d_in[5];
    const float* eb1   = (const float*)d_in[6];
    const float* ew2   = (const float*)d_in[7];
    const float* eb2   = (const float*)d_in[8];
    const float* attw  = (const float*)d_in[9];
    const float* attb  = (const float*)d_in[10];
    const float* nw1   = (const float*)d_in[11];
    const float* nb1   = (const float*)d_in[12];
    const float* nw2   = (const float*)d_in[13];
    const float* nb2   = (const float*)d_in[14];
    const float* cw1   = (const float*)d_in[15];
    const float* cb1   = (const float*)d_in[16];
    const float* cw2   = (const float*)d_in[17];
    const float* fc1w  = (const float*)d_in[18];
    const float* fc1b  = (const float*)d_in[19];
    const float* fc2w  = (const float*)d_in[20];
    const float* fc2b  = (const float*)d_in[21];
    // d_in[22], d_in[23] = edge_row/edge_col (recomputed analytically)

    pack_mma_kernel<<<48, 256>>>(ew2, cw1);
    pack_node_kernel<<<256, 256>>>(ew1, nw1, nw2, fc1w);

    const size_t smem_bytes = (size_t)SMEM_FLOATS * sizeof(float);
    cudaFuncSetAttribute(egnn_critic_kernel,
                         cudaFuncAttributeMaxDynamicSharedMemorySize,
                         (int)smem_bytes);

    int copy_rnn = (out_size >= NB + NB*HID) ? 1 : 0;

    egnn_critic_kernel<<<NB, BLK, smem_bytes>>>(
        obs, rnn, emb_w, emb_b, ew1, eb1, ew2, eb2, attw, attb,
        nw1, nb1, nw2, nb2, cw1, cb1, cw2, fc1w, fc1b, fc2w, fc2b,
        (float*)d_out, copy_rnn);
}